// round 15
// baseline (speedup 1.0000x reference)
#include <cuda_runtime.h>
#include <cuda_bf16.h>
#include <cstdint>
#include <float.h>

// ---------------------------------------------------------------- problem dims
#define B_  32
#define D_  256
#define K_  8192
#define HW  1024
#define N_  32768
#define OUT_ELEMS 8388608
#define LOSS_OFF  OUT_ELEMS
#define IDX_OFF   (OUT_ELEMS + 1)

// ---------------------------------------------------------------- GEMM tiling
// M-tile 64, chunks of 64 codes, occupancy 2 (two independent CTAs per SM).
#define MTILE 64
#define NCHUNK 128                   // 128 chunks of 64 codes
#define AROWB 528                    // bytes per A smem row (256 bf16 + 8 pad)
#define BROWB 144                    // bytes per B smem row (64 bf16 + 8 pad)
#define BUFB (256 * BROWB)           // 36864 bytes per B buffer
#define SM_A 0
#define SM_B (MTILE * AROWB)         // 33792
#define SM_TOTAL (SM_B + 2 * BUFB)   // 107520 -> 2 CTAs/SM = 215040 <= 233472

#define EBIAS 1024.0f                // keeps packed scores positive (monotone bits)

// ---------------------------------------------------------------- scratch
__device__ __align__(16) float g_enorm[K_];                       // ||e||^2 + EBIAS
__device__ __align__(16) int   g_idx[N_];
__device__ __align__(16) float g_part[1024];
__device__ __align__(16) int   g_top4[N_ * 4];
__device__ __align__(16) __nv_bfloat16 g_latT[(size_t)N_ * D_];   // [n][d] bf16
__device__ __align__(16) __nv_bfloat16 g_embBf[(size_t)D_ * K_];  // [d][k] bf16
__device__ __align__(16) float g_embT[(size_t)K_ * D_];           // [k][d] fp32

// ---------------------------------------------------------------- helpers
__device__ __forceinline__ uint32_t smem_u32(const void* p) {
    return (uint32_t)__cvta_generic_to_shared(p);
}
__device__ __forceinline__ void cp_async16(uint32_t dst, const void* src) {
    asm volatile("cp.async.cg.shared.global [%0], [%1], 16;" :: "r"(dst), "l"(src));
}
__device__ __forceinline__ void ldsm_x4(uint32_t* r, uint32_t addr) {
    asm volatile("ldmatrix.sync.aligned.m8n8.x4.shared.b16 {%0,%1,%2,%3}, [%4];"
                 : "=r"(r[0]), "=r"(r[1]), "=r"(r[2]), "=r"(r[3]) : "r"(addr));
}
__device__ __forceinline__ void ldsm_x4_t(uint32_t* r, uint32_t addr) {
    asm volatile("ldmatrix.sync.aligned.m8n8.x4.trans.shared.b16 {%0,%1,%2,%3}, [%4];"
                 : "=r"(r[0]), "=r"(r[1]), "=r"(r[2]), "=r"(r[3]) : "r"(addr));
}
__device__ __forceinline__ void mma_bf16(float* c, const uint32_t* a, uint32_t b0, uint32_t b1) {
    asm volatile(
        "mma.sync.aligned.m16n8k16.row.col.f32.bf16.bf16.f32 "
        "{%0,%1,%2,%3}, {%4,%5,%6,%7}, {%8,%9}, {%0,%1,%2,%3};"
        : "+f"(c[0]), "+f"(c[1]), "+f"(c[2]), "+f"(c[3])
        : "r"(a[0]), "r"(a[1]), "r"(a[2]), "r"(a[3]), "r"(b0), "r"(b1));
}
#define WAITG(n) asm volatile("cp.async.wait_group %0;" :: "n"(n) : "memory")

// ---------------------------------------------------------------- kernel 1: embconv + enorm fused
__global__ __launch_bounds__(256)
void embprep_kernel(const float* __restrict__ emb) {
    int k = blockIdx.x * 256 + threadIdx.x;
    float s = 0.f;
#pragma unroll 8
    for (int d = 0; d < D_; ++d) {
        float v = emb[(size_t)d * K_ + k];
        s = fmaf(v, v, s);
        g_embBf[(size_t)d * K_ + k] = __float2bfloat16(v);
    }
    g_enorm[k] = s + EBIAS;   // constant bias: argmin invariant
}

// ---------------------------------------------------------------- kernel 2: latents -> bf16 [n][d]
__global__ void latconv_kernel(const float* __restrict__ lat) {
    __shared__ float t[32][33];
    int b = blockIdx.z, hw0 = blockIdx.x * 32, d0 = blockIdx.y * 32;
    t[threadIdx.y][threadIdx.x] =
        lat[((size_t)b * D_ + d0 + threadIdx.y) * HW + hw0 + threadIdx.x];
    __syncthreads();
    g_latT[((size_t)(b * HW + hw0 + threadIdx.y)) * D_ + d0 + threadIdx.x] =
        __float2bfloat16(t[threadIdx.x][threadIdx.y]);
}

// ---------------------------------------------------------------- kernel 3: embeddings -> fp32 [k][d]
__global__ void embT_kernel(const float* __restrict__ emb) {
    __shared__ float t[32][33];
    int kb = blockIdx.x * 32, db = blockIdx.y * 32;
    t[threadIdx.y][threadIdx.x] = emb[(size_t)(db + threadIdx.y) * K_ + kb + threadIdx.x];
    __syncthreads();
    g_embT[(size_t)(kb + threadIdx.y) * D_ + db + threadIdx.x] = t[threadIdx.x][threadIdx.y];
}

// ---------------------------------------------------------------- kernel 4 support
// B chunk prefetch: 256 d-rows x 64 codes bf16 (128B data per row).
__device__ __forceinline__ void prefetch_B(uint32_t sb, int tid, int u, int buf) {
    const char* bt = (const char*)g_embBf + (size_t)u * 128;   // col offset u*64 codes
    uint32_t bd = sb + SM_B + buf * BUFB;
#pragma unroll
    for (int j = 0; j < 8; ++j) {
        int i = j * 256 + tid;
        int r = i >> 3, s = i & 7;
        cp_async16(bd + r * BROWB + s * 16, bt + (size_t)r * (K_ * 2) + s * 16);
    }
    asm volatile("cp.async.commit_group;" ::: "memory");
}

// Packed top-2: truncated positive score bits | 9-bit local id; umin/umax only.
#define TOP2P(rs, scf, c9)                                          \
    {                                                               \
        uint32_t pv_ = (__float_as_uint(scf) & 0xFFFFFE00u) | (c9); \
        uint32_t mx_ = p0[rs] > pv_ ? p0[rs] : pv_;                 \
        p1[rs] = p1[rs] < mx_ ? p1[rs] : mx_;                       \
        p0[rs] = p0[rs] < pv_ ? p0[rs] : pv_;                       \
    }

// decode 9-bit local id (u*4 + nf*2 + q) back to a global column
__device__ __forceinline__ int dec9(uint32_t p, int wn, int l3) {
    int loc = p & 0x1FF;
    int u = loc >> 2, j = loc & 3;
    return u * 64 + wn * 16 + (j >> 1) * 8 + l3 * 2 + (j & 1);
}

// ---------------------------------------------------------------- kernel 4: bf16 mma.sync GEMM, occ=2
// 256 threads, 8 warps in 2(M) x 4(N); warp tile 32x16. Single accumulator,
// standalone epilogue: the sibling CTA on the same SM (occupancy 2, no shared
// barriers) fills every sync/epilogue bubble with its own MMAs.
__global__ __launch_bounds__(256, 2)
void vq_mma_kernel() {
    extern __shared__ char smem[];
    const uint32_t sb = smem_u32(smem);
    const int tid = threadIdx.x, lane = tid & 31, wid = tid >> 5;
    const int wm = wid & 1;        // 0-1: 32-row half (M)
    const int wn = wid >> 1;       // 0-3: 16-col quarter (N)
    const int l3 = lane & 3;

    // ---- prologue: A tile (64x256 bf16) + B chunk 0 in group0; chunk 1 group1
    {
        const char* at = (const char*)(g_latT + (size_t)blockIdx.x * MTILE * D_);
#pragma unroll
        for (int j = 0; j < 8; ++j) {
            int i = j * 256 + tid;
            int r = i >> 5, s = i & 31;
            cp_async16(sb + SM_A + r * AROWB + s * 16, at + (size_t)r * 512 + s * 16);
        }
    }
    prefetch_B(sb, tid, 0, 0);     // commits A + B0 as group0
    prefetch_B(sb, tid, 1, 1);     // group1

    // A ldmatrix addrs: rows wm*32 + mf*16 + (lane&15), k-half (lane>>4)*16B
    uint32_t a_addr[2];
#pragma unroll
    for (int mf = 0; mf < 2; ++mf)
        a_addr[mf] = sb + SM_A + (wm * 32 + mf * 16 + (lane & 15)) * AROWB
                   + (lane >> 4) * 16;
    // B ldmatrix (trans) within buffer: k-row ((lane>>3)&1)*8+(lane&7),
    // col-half (lane>>4)*8 cols, pair stripe wn*16 cols
    const uint32_t b_off = ((((lane >> 3) & 1) * 8 + (lane & 7)) * BROWB)
                         + (lane >> 4) * 16 + wn * 32;

    uint32_t p0[4], p1[4];
#pragma unroll
    for (int r = 0; r < 4; ++r) { p0[r] = 0xFFFFFFFFu; p1[r] = 0xFFFFFFFFu; }

    WAITG(1);                      // A + B0 landed (own thread)
    __syncthreads();               // visible block-wide

    for (int u = 0; u < NCHUNK; ++u) {
        const uint32_t bbase = sb + SM_B + (u & 1) * BUFB + b_off;

        float acc[2][2][4];
#pragma unroll
        for (int mf = 0; mf < 2; ++mf)
#pragma unroll
            for (int nf = 0; nf < 2; ++nf)
#pragma unroll
                for (int q = 0; q < 4; ++q) acc[mf][nf][q] = 0.f;

#pragma unroll
        for (int ks = 0; ks < 16; ++ks) {
            uint32_t ar[2][4];
#pragma unroll
            for (int mf = 0; mf < 2; ++mf) ldsm_x4(ar[mf], a_addr[mf] + ks * 32);
            uint32_t br[4];
            ldsm_x4_t(br, bbase + ks * 16 * BROWB);
#pragma unroll
            for (int mf = 0; mf < 2; ++mf)
#pragma unroll
                for (int nf = 0; nf < 2; ++nf)
                    mma_bf16(acc[mf][nf], ar[mf], br[nf * 2], br[nf * 2 + 1]);
        }

        // epilogue: sc = enorm[c] - 2*dot; packed top-2 per (thread,row)
#pragma unroll
        for (int nf = 0; nf < 2; ++nf) {
            const int c0 = (u << 6) + wn * 16 + nf * 8 + l3 * 2;
            const uint32_t c9 = (uint32_t)((u << 2) + nf * 2);
            float2 e = __ldg(reinterpret_cast<const float2*>(&g_enorm[c0]));
#pragma unroll
            for (int mf = 0; mf < 2; ++mf)
#pragma unroll
                for (int half = 0; half < 2; ++half) {
                    const int rs = mf * 2 + half;
                    float s0 = fmaf(-2.f, acc[mf][nf][half * 2 + 0], e.x);
                    float s1 = fmaf(-2.f, acc[mf][nf][half * 2 + 1], e.y);
                    TOP2P(rs, s0, c9);
                    TOP2P(rs, s1, c9 + 1);
                }
        }

        __syncthreads();                        // all warps done reading buf(u&1)
        if (u + 2 < NCHUNK) {
            prefetch_B(sb, tid, u + 2, u & 1);  // refill the buffer just drained
            WAITG(1);                           // chunk u+1's group landed
        } else if (u + 1 < NCHUNK) {
            WAITG(0);                           // last chunk's group landed
        }
        if (u + 1 < NCHUNK) __syncthreads();    // visible block-wide
    }

    // ---- merge: 16 subsets x top-2 = 32 candidates per row -> top-4
    struct Pair { uint32_t v; int i; };
    Pair* pr = reinterpret_cast<Pair*>(smem);   // [64][32] = 16KB (A region done)
    __syncthreads();
#pragma unroll
    for (int rs = 0; rs < 4; ++rs) {
        int r = wm * 32 + (rs >> 1) * 16 + (lane >> 2) + (rs & 1) * 8;
        int sub = wn * 4 + l3;
        pr[r * 32 + sub * 2 + 0] = { p0[rs] & 0xFFFFFE00u, dec9(p0[rs], wn, l3) };
        pr[r * 32 + sub * 2 + 1] = { p1[rs] & 0xFFFFFE00u, dec9(p1[rs], wn, l3) };
    }
    __syncthreads();
    if (tid < MTILE) {
        uint32_t bv[4] = {0xFFFFFFFFu, 0xFFFFFFFFu, 0xFFFFFFFFu, 0xFFFFFFFFu};
        int      bi[4] = {0x7fffffff, 0x7fffffff, 0x7fffffff, 0x7fffffff};
        for (int j = 0; j < 32; ++j) {
            uint32_t v = pr[tid * 32 + j].v;
            int      i = pr[tid * 32 + j].i;
            if (v < bv[3] || (v == bv[3] && i < bi[3])) {
                if (v < bv[0] || (v == bv[0] && i < bi[0])) {
                    bv[3]=bv[2]; bi[3]=bi[2]; bv[2]=bv[1]; bi[2]=bi[1];
                    bv[1]=bv[0]; bi[1]=bi[0]; bv[0]=v; bi[0]=i;
                } else if (v < bv[1] || (v == bv[1] && i < bi[1])) {
                    bv[3]=bv[2]; bi[3]=bi[2]; bv[2]=bv[1]; bi[2]=bi[1];
                    bv[1]=v; bi[1]=i;
                } else if (v < bv[2] || (v == bv[2] && i < bi[2])) {
                    bv[3]=bv[2]; bi[3]=bi[2]; bv[2]=v; bi[2]=i;
                } else {
                    bv[3]=v; bi[3]=i;
                }
            }
        }
        int row = blockIdx.x * MTILE + tid;
#pragma unroll
        for (int s = 0; s < 4; ++s) g_top4[row * 4 + s] = bi[s];
    }
}

// ---------------------------------------------------------------- kernel 5: fused exact rescore + gather + loss partials
#define SMF_Z 0
#define SMF_E (32 * 257)
#define SMF_TOTAL ((2 * 32 * 257 + 32 + 256) * 4)
__global__ __launch_bounds__(256)
void rescore_gather_kernel(const float* __restrict__ lat,
                           float* __restrict__ out, float* __restrict__ out_idx_f) {
    extern __shared__ float sm[];
    float* zt = sm + SMF_Z;            // [32 w][257 d] fp32 latents
    float* et = sm + SMF_E;            // [32 w][257 d] gathered embeddings
    int*   sidx = (int*)(sm + 2 * 32 * 257);
    float* red  = sm + 2 * 32 * 257 + 32;

    int bh = blockIdx.x;               // (b,h)
    int b = bh >> 5, h = bh & 31;
    int t = threadIdx.x;
    int w = t & 31, dq = t >> 5;

    size_t base = (size_t)b * (D_ * HW) + h * 32;
#pragma unroll 4
    for (int i = 0; i < 32; ++i) {
        int d = i * 8 + dq;
        zt[w * 257 + d] = lat[base + (size_t)d * HW + w];
    }
    __syncthreads();

    // phase 1: exact fp32 rescore — 8 threads per row
    {
        int rl = t >> 3, l8 = t & 7;
        int row = bh * 32 + rl;
        int cand[4];
#pragma unroll
        for (int c = 0; c < 4; ++c) cand[c] = g_top4[row * 4 + c];
        float dot[4] = {0.f, 0.f, 0.f, 0.f};
        for (int d = l8; d < D_; d += 8) {
            float zv = zt[rl * 257 + d];
#pragma unroll
            for (int c = 0; c < 4; ++c)
                dot[c] = fmaf(zv, g_embT[(size_t)cand[c] * D_ + d], dot[c]);
        }
#pragma unroll
        for (int c = 0; c < 4; ++c) {
#pragma unroll
            for (int off = 4; off > 0; off >>= 1)
                dot[c] += __shfl_down_sync(0xffffffffu, dot[c], off, 8);
        }
        if (l8 == 0) {
            float bv = FLT_MAX; int bi = 0x7fffffff;
#pragma unroll
            for (int c = 0; c < 4; ++c) {
                float dist = fmaf(-2.f, dot[c], g_enorm[cand[c]]);  // bias: invariant
                if (dist < bv || (dist == bv && cand[c] < bi)) { bv = dist; bi = cand[c]; }
            }
            g_idx[row] = bi;
            sidx[rl] = bi;
            out_idx_f[row] = (float)bi;
        }
    }
    __syncthreads();

#pragma unroll 4
    for (int i = 0; i < 32; ++i)
        et[i * 257 + t] = g_embT[(size_t)sidx[i] * D_ + t];
    __syncthreads();

    float lsum = 0.f;
#pragma unroll 4
    for (int i = 0; i < 32; ++i) {
        int d = i * 8 + dq;
        float v = et[w * 257 + d];
        float x = zt[w * 257 + d];
        out[base + (size_t)d * HW + w] = v;
        float df = v - x;
        lsum = fmaf(df, df, lsum);
    }
    red[t] = lsum;
    __syncthreads();
    for (int st = 128; st > 0; st >>= 1) {
        if (t < st) red[t] += red[t + st];
        __syncthreads();
    }
    if (t == 0) g_part[bh] = red[0];
}

// ---------------------------------------------------------------- kernel 6: final loss
__global__ void loss_kernel(float* __restrict__ out_loss) {
    __shared__ float red[1024];
    int t = threadIdx.x;
    red[t] = g_part[t];
    __syncthreads();
    for (int st = 512; st > 0; st >>= 1) {
        if (t < st) red[t] += red[t + st];
        __syncthreads();
    }
    if (t == 0) out_loss[0] = 1.25f * (red[0] / 8388608.0f);
}

// ----------------------------------------------------------------
extern "C" void kernel_launch(void* const* d_in, const int* in_sizes, int n_in,
                              void* d_out, int out_size) {
    const float* lat = (const float*)d_in[0];
    const float* emb = (const float*)d_in[1];
    if (n_in >= 2 && in_sizes[0] == D_ * K_) {   // defensive size-based ident
        lat = (const float*)d_in[1];
        emb = (const float*)d_in[0];
    }
    float* out = (float*)d_out;

    embprep_kernel<<<K_ / 256, 256>>>(emb);
    latconv_kernel<<<dim3(HW / 32, D_ / 32, B_), dim3(32, 32)>>>(lat);
    embT_kernel<<<dim3(K_ / 32, D_ / 32), dim3(32, 32)>>>(emb);

    // vq_mma stays the 4th launch so ncu's skip window profiles it.
    cudaFuncSetAttribute(vq_mma_kernel,
                         cudaFuncAttributeMaxDynamicSharedMemorySize, SM_TOTAL);
    vq_mma_kernel<<<N_ / MTILE, 256, SM_TOTAL>>>();

    cudaFuncSetAttribute(rescore_gather_kernel,
                         cudaFuncAttributeMaxDynamicSharedMemorySize, SMF_TOTAL);
    rescore_gather_kernel<<<B_ * 32, 256, SMF_TOTAL>>>(lat, out, out + IDX_OFF);
    loss_kernel<<<1, 1024>>>(out + LOSS_OFF);
}

// round 16
// speedup vs baseline: 1.2132x; 1.2132x over previous
#include <cuda_runtime.h>
#include <cuda_bf16.h>
#include <cstdint>
#include <float.h>

// ---------------------------------------------------------------- problem dims
#define B_  32
#define D_  256
#define K_  8192
#define HW  1024
#define N_  32768
#define OUT_ELEMS 8388608
#define LOSS_OFF  OUT_ELEMS
#define IDX_OFF   (OUT_ELEMS + 1)

// ---------------------------------------------------------------- GEMM tiling
// 128x128 CTA tile, 512 threads, warp grid 4(M) x 4(N), warp tile 32x32.
// Each N-quad (4 warps, one per SMSP) owns a private 32-col B slice ring.
#define NCHUNK 64                    // 64 chunks of 128 codes (32 per quad)
#define AROWB 528                    // bytes per A smem row (256 bf16 + 8 pad)
#define SLROW 80                     // bytes per B-slice row (64B data + 16 pad)
#define SLICE_BUF (256 * SLROW)      // 20480: one 256-d x 32-code slice
#define SM_A 0
#define SM_S (128 * AROWB)           // 67584
#define SM_TOTAL (SM_S + 8 * SLICE_BUF)  // 231424 <= 232448

#define EBIAS 1024.0f                // keeps packed scores positive (monotone bits)

// ---------------------------------------------------------------- scratch
__device__ __align__(16) float g_enorm[K_];                       // ||e||^2 + EBIAS
__device__ __align__(16) int   g_idx[N_];
__device__ __align__(16) float g_part[1024];
__device__ __align__(16) int   g_top4[N_ * 4];
__device__ __align__(16) __nv_bfloat16 g_latT[(size_t)N_ * D_];   // [n][d] bf16
__device__ __align__(16) __nv_bfloat16 g_embBf[(size_t)D_ * K_];  // [d][k] bf16
__device__ __align__(16) float g_embT[(size_t)K_ * D_];           // [k][d] fp32

// ---------------------------------------------------------------- helpers
__device__ __forceinline__ uint32_t smem_u32(const void* p) {
    return (uint32_t)__cvta_generic_to_shared(p);
}
__device__ __forceinline__ void cp_async16(uint32_t dst, const void* src) {
    asm volatile("cp.async.cg.shared.global [%0], [%1], 16;" :: "r"(dst), "l"(src));
}
__device__ __forceinline__ void ldsm_x4(uint32_t* r, uint32_t addr) {
    asm volatile("ldmatrix.sync.aligned.m8n8.x4.shared.b16 {%0,%1,%2,%3}, [%4];"
                 : "=r"(r[0]), "=r"(r[1]), "=r"(r[2]), "=r"(r[3]) : "r"(addr));
}
__device__ __forceinline__ void ldsm_x4_t(uint32_t* r, uint32_t addr) {
    asm volatile("ldmatrix.sync.aligned.m8n8.x4.trans.shared.b16 {%0,%1,%2,%3}, [%4];"
                 : "=r"(r[0]), "=r"(r[1]), "=r"(r[2]), "=r"(r[3]) : "r"(addr));
}
__device__ __forceinline__ void mma_bf16(float* c, const uint32_t* a, uint32_t b0, uint32_t b1) {
    asm volatile(
        "mma.sync.aligned.m16n8k16.row.col.f32.bf16.bf16.f32 "
        "{%0,%1,%2,%3}, {%4,%5,%6,%7}, {%8,%9}, {%0,%1,%2,%3};"
        : "+f"(c[0]), "+f"(c[1]), "+f"(c[2]), "+f"(c[3])
        : "r"(a[0]), "r"(a[1]), "r"(a[2]), "r"(a[3]), "r"(b0), "r"(b1));
}
// quad barrier: the 4 warps (one per SMSP) sharing N-stripe wn
#define QUAD_BAR(wn) \
    asm volatile("bar.sync %0, 128;" :: "r"(1 + (wn)) : "memory")
#define WAITG(n) asm volatile("cp.async.wait_group %0;" :: "n"(n) : "memory")

// ---------------------------------------------------------------- kernel 1: embconv + enorm fused
__global__ __launch_bounds__(256)
void embprep_kernel(const float* __restrict__ emb) {
    int k = blockIdx.x * 256 + threadIdx.x;
    float s = 0.f;
#pragma unroll 8
    for (int d = 0; d < D_; ++d) {
        float v = emb[(size_t)d * K_ + k];
        s = fmaf(v, v, s);
        g_embBf[(size_t)d * K_ + k] = __float2bfloat16(v);
    }
    g_enorm[k] = s + EBIAS;   // constant bias: argmin invariant
}

// ---------------------------------------------------------------- kernel 2: latents -> bf16 [n][d]
__global__ void latconv_kernel(const float* __restrict__ lat) {
    __shared__ float t[32][33];
    int b = blockIdx.z, hw0 = blockIdx.x * 32, d0 = blockIdx.y * 32;
    t[threadIdx.y][threadIdx.x] =
        lat[((size_t)b * D_ + d0 + threadIdx.y) * HW + hw0 + threadIdx.x];
    __syncthreads();
    g_latT[((size_t)(b * HW + hw0 + threadIdx.y)) * D_ + d0 + threadIdx.x] =
        __float2bfloat16(t[threadIdx.x][threadIdx.y]);
}

// ---------------------------------------------------------------- kernel 3: embeddings -> fp32 [k][d]
__global__ void embT_kernel(const float* __restrict__ emb) {
    __shared__ float t[32][33];
    int kb = blockIdx.x * 32, db = blockIdx.y * 32;
    t[threadIdx.y][threadIdx.x] = emb[(size_t)(db + threadIdx.y) * K_ + kb + threadIdx.x];
    __syncthreads();
    g_embT[(size_t)(kb + threadIdx.y) * D_ + db + threadIdx.x] = t[threadIdx.x][threadIdx.y];
}

// ---------------------------------------------------------------- kernel 4 support
// Quad slice prefetch: 256 d-rows x 32 codes (64B/row as 4 x 16B), 128 threads.
__device__ __forceinline__ void prefetch_slice(uint32_t bufaddr, int qid,
                                               int code_off) {
    const char* base = (const char*)g_embBf + (size_t)code_off * 2;
#pragma unroll
    for (int j = 0; j < 8; ++j) {
        int idx = j * 128 + qid;
        int r = idx >> 2, s = idx & 3;
        cp_async16(bufaddr + r * SLROW + s * 16, base + (size_t)r * (K_ * 2) + s * 16);
    }
    asm volatile("cp.async.commit_group;" ::: "memory");
}

// Packed top-2: truncated positive score bits | 9-bit local id; umin/umax only.
#define TOP2P(rs, scf, c9)                                          \
    {                                                               \
        uint32_t pv_ = (__float_as_uint(scf) & 0xFFFFFE00u) | (c9); \
        uint32_t mx_ = p0[rs] > pv_ ? p0[rs] : pv_;                 \
        p1[rs] = p1[rs] < mx_ ? p1[rs] : mx_;                       \
        p0[rs] = p0[rs] < pv_ ? p0[rs] : pv_;                       \
    }

// decode 9-bit local id (u<<3 | nf*2 + q) back to a global column
__device__ __forceinline__ int dec9(uint32_t p, int wn, int l3) {
    int loc = p & 0x1FF;
    int u = loc >> 3, jj = loc & 7;
    return u * 128 + wn * 32 + l3 * 2 + (jj >> 1) * 8 + (jj & 1);
}

// ---------------------------------------------------------------- kernel 4: bf16 mma.sync GEMM, quad-decoupled, 512 threads
__global__ __launch_bounds__(512, 1)
void vq_mma_kernel() {
    extern __shared__ char smem[];
    const uint32_t sb = smem_u32(smem);
    const int tid = threadIdx.x, lane = tid & 31, wid = tid >> 5;
    const int wm = wid & 3;        // 0-3: 32-row quarter (M); also SMSP id
    const int wn = wid >> 2;       // 0-3: 32-col quarter (N) = quad id
    const int l3 = lane & 3;
    const int qid = (wm << 5) | lane;   // 0..127 within quad

    const uint32_t quad_base = sb + SM_S + wn * (2 * SLICE_BUF);
    const uint32_t buf0 = quad_base, buf1 = quad_base + SLICE_BUF;
    const int colc = wn * 32;      // quad's code offset within a chunk

    // ---- prologue: A tile (128x256 bf16) + slice(chunk0) = group0; slice1 = group1
    {
        const char* at = (const char*)(g_latT + (size_t)blockIdx.x * 128 * D_);
#pragma unroll
        for (int j = 0; j < 8; ++j) {
            int i = j * 512 + tid;
            int r = i >> 5, s = i & 31;
            cp_async16(sb + SM_A + r * AROWB + s * 16, at + (size_t)r * 512 + s * 16);
        }
    }
    prefetch_slice(buf0, qid, 0 * 128 + colc);   // commits A + slice0 as group0
    prefetch_slice(buf1, qid, 1 * 128 + colc);   // group1

    // A ldmatrix addrs: rows wm*32 + mf*16 + (lane&15); k-half (lane>>4)*16B
    uint32_t a_addr[2];
#pragma unroll
    for (int mf = 0; mf < 2; ++mf)
        a_addr[mf] = sb + SM_A + (wm * 32 + mf * 16 + (lane & 15)) * AROWB
                   + (lane >> 4) * 16;
    // B ldsm (trans) within slice (geometry identical to R12, bit-validated)
    const uint32_t b_off = ((((lane >> 3) & 1) * 8 + (lane & 7)) * SLROW)
                         + (lane >> 4) * 16;
    const int cb_lane = wn * 32 + l3 * 2;

    uint32_t p0[4], p1[4];
#pragma unroll
    for (int r = 0; r < 4; ++r) { p0[r] = 0xFFFFFFFFu; p1[r] = 0xFFFFFFFFu; }

    WAITG(1);                      // A + slice0 landed (own thread)
    __syncthreads();               // block-wide visibility (A from all threads)

    for (int u = 0; u < NCHUNK; ++u) {
        const uint32_t bbase = (u & 1 ? buf1 : buf0) + b_off;

        float acc[2][4][4];
#pragma unroll
        for (int mf = 0; mf < 2; ++mf)
#pragma unroll
            for (int nf = 0; nf < 4; ++nf)
#pragma unroll
                for (int q = 0; q < 4; ++q) acc[mf][nf][q] = 0.f;

#pragma unroll
        for (int ks = 0; ks < 16; ++ks) {
            uint32_t ar[2][4];
#pragma unroll
            for (int mf = 0; mf < 2; ++mf) ldsm_x4(ar[mf], a_addr[mf] + ks * 32);
            uint32_t br[2][4];
#pragma unroll
            for (int p = 0; p < 2; ++p)
                ldsm_x4_t(br[p], bbase + ks * 16 * SLROW + p * 32);
#pragma unroll
            for (int mf = 0; mf < 2; ++mf)
#pragma unroll
                for (int nf = 0; nf < 4; ++nf)
                    mma_bf16(acc[mf][nf], ar[mf],
                             br[nf >> 1][(nf & 1) * 2], br[nf >> 1][(nf & 1) * 2 + 1]);
        }

        // epilogue: sc = enorm[c] - 2*dot; packed top-2. (Cross-quad overlap
        // hides this: other quads' warps on the same SMSP keep issuing MMAs.)
#pragma unroll
        for (int nf = 0; nf < 4; ++nf) {
            const int c0 = (u << 7) + cb_lane + nf * 8;
            const uint32_t c9 = (uint32_t)((u << 3) + nf * 2);
            float2 e = __ldg(reinterpret_cast<const float2*>(&g_enorm[c0]));
#pragma unroll
            for (int mf = 0; mf < 2; ++mf)
#pragma unroll
                for (int half = 0; half < 2; ++half) {
                    const int rs = mf * 2 + half;
                    float s0 = fmaf(-2.f, acc[mf][nf][half * 2 + 0], e.x);
                    float s1 = fmaf(-2.f, acc[mf][nf][half * 2 + 1], e.y);
                    TOP2P(rs, s0, c9);
                    TOP2P(rs, s1, c9 + 1);
                }
        }

        QUAD_BAR(wn);                           // quad done reading buf(u&1)
        if (u + 2 < NCHUNK) {
            prefetch_slice(u & 1 ? buf1 : buf0, qid, (u + 2) * 128 + colc);
            WAITG(1);                           // slice(u+1) landed (own thread)
        } else if (u + 1 < NCHUNK) {
            WAITG(0);                           // final slice landed
        }
        if (u + 1 < NCHUNK) QUAD_BAR(wn);       // quad-wide visibility
    }

    // ---- merge: 16 subsets x top-2 = 32 candidates per row -> top-4
    struct Pair { uint32_t v; int i; };
    Pair* pr = reinterpret_cast<Pair*>(smem);   // [128][32] = 32KB (A region done)
    __syncthreads();
#pragma unroll
    for (int rs = 0; rs < 4; ++rs) {
        int r = wm * 32 + (rs >> 1) * 16 + (rs & 1) * 8 + (lane >> 2);
        int sub = wn * 4 + l3;
        pr[r * 32 + sub * 2 + 0] = { p0[rs] & 0xFFFFFE00u, dec9(p0[rs], wn, l3) };
        pr[r * 32 + sub * 2 + 1] = { p1[rs] & 0xFFFFFE00u, dec9(p1[rs], wn, l3) };
    }
    __syncthreads();
    if (tid < 128) {
        uint32_t bv[4] = {0xFFFFFFFFu, 0xFFFFFFFFu, 0xFFFFFFFFu, 0xFFFFFFFFu};
        int      bi[4] = {0x7fffffff, 0x7fffffff, 0x7fffffff, 0x7fffffff};
        for (int j = 0; j < 32; ++j) {
            uint32_t v = pr[tid * 32 + j].v;
            int      i = pr[tid * 32 + j].i;
            if (v < bv[3] || (v == bv[3] && i < bi[3])) {
                if (v < bv[0] || (v == bv[0] && i < bi[0])) {
                    bv[3]=bv[2]; bi[3]=bi[2]; bv[2]=bv[1]; bi[2]=bi[1];
                    bv[1]=bv[0]; bi[1]=bi[0]; bv[0]=v; bi[0]=i;
                } else if (v < bv[1] || (v == bv[1] && i < bi[1])) {
                    bv[3]=bv[2]; bi[3]=bi[2]; bv[2]=bv[1]; bi[2]=bi[1];
                    bv[1]=v; bi[1]=i;
                } else if (v < bv[2] || (v == bv[2] && i < bi[2])) {
                    bv[3]=bv[2]; bi[3]=bi[2]; bv[2]=v; bi[2]=i;
                } else {
                    bv[3]=v; bi[3]=i;
                }
            }
        }
        int row = blockIdx.x * 128 + tid;
#pragma unroll
        for (int s = 0; s < 4; ++s) g_top4[row * 4 + s] = bi[s];
    }
}

// ---------------------------------------------------------------- kernel 5: fused exact rescore + gather + loss partials
#define SMF_Z 0
#define SMF_E (32 * 257)
#define SMF_TOTAL ((2 * 32 * 257 + 32 + 256) * 4)
__global__ __launch_bounds__(256)
void rescore_gather_kernel(const float* __restrict__ lat,
                           float* __restrict__ out, float* __restrict__ out_idx_f) {
    extern __shared__ float sm[];
    float* zt = sm + SMF_Z;            // [32 w][257 d] fp32 latents
    float* et = sm + SMF_E;            // [32 w][257 d] gathered embeddings
    int*   sidx = (int*)(sm + 2 * 32 * 257);
    float* red  = sm + 2 * 32 * 257 + 32;

    int bh = blockIdx.x;               // (b,h)
    int b = bh >> 5, h = bh & 31;
    int t = threadIdx.x;
    int w = t & 31, dq = t >> 5;

    size_t base = (size_t)b * (D_ * HW) + h * 32;
#pragma unroll 4
    for (int i = 0; i < 32; ++i) {
        int d = i * 8 + dq;
        zt[w * 257 + d] = lat[base + (size_t)d * HW + w];
    }
    __syncthreads();

    // phase 1: exact fp32 rescore — 8 threads per row
    {
        int rl = t >> 3, l8 = t & 7;
        int row = bh * 32 + rl;
        int cand[4];
#pragma unroll
        for (int c = 0; c < 4; ++c) cand[c] = g_top4[row * 4 + c];
        float dot[4] = {0.f, 0.f, 0.f, 0.f};
        for (int d = l8; d < D_; d += 8) {
            float zv = zt[rl * 257 + d];
#pragma unroll
            for (int c = 0; c < 4; ++c)
                dot[c] = fmaf(zv, g_embT[(size_t)cand[c] * D_ + d], dot[c]);
        }
#pragma unroll
        for (int c = 0; c < 4; ++c) {
#pragma unroll
            for (int off = 4; off > 0; off >>= 1)
                dot[c] += __shfl_down_sync(0xffffffffu, dot[c], off, 8);
        }
        if (l8 == 0) {
            float bv = FLT_MAX; int bi = 0x7fffffff;
#pragma unroll
            for (int c = 0; c < 4; ++c) {
                float dist = fmaf(-2.f, dot[c], g_enorm[cand[c]]);  // bias: invariant
                if (dist < bv || (dist == bv && cand[c] < bi)) { bv = dist; bi = cand[c]; }
            }
            g_idx[row] = bi;
            sidx[rl] = bi;
            out_idx_f[row] = (float)bi;
        }
    }
    __syncthreads();

#pragma unroll 4
    for (int i = 0; i < 32; ++i)
        et[i * 257 + t] = g_embT[(size_t)sidx[i] * D_ + t];
    __syncthreads();

    float lsum = 0.f;
#pragma unroll 4
    for (int i = 0; i < 32; ++i) {
        int d = i * 8 + dq;
        float v = et[w * 257 + d];
        float x = zt[w * 257 + d];
        out[base + (size_t)d * HW + w] = v;
        float df = v - x;
        lsum = fmaf(df, df, lsum);
    }
    red[t] = lsum;
    __syncthreads();
    for (int st = 128; st > 0; st >>= 1) {
        if (t < st) red[t] += red[t + st];
        __syncthreads();
    }
    if (t == 0) g_part[bh] = red[0];
}

// ---------------------------------------------------------------- kernel 6: final loss
__global__ void loss_kernel(float* __restrict__ out_loss) {
    __shared__ float red[1024];
    int t = threadIdx.x;
    red[t] = g_part[t];
    __syncthreads();
    for (int st = 512; st > 0; st >>= 1) {
        if (t < st) red[t] += red[t + st];
        __syncthreads();
    }
    if (t == 0) out_loss[0] = 1.25f * (red[0] / 8388608.0f);
}

// ----------------------------------------------------------------
extern "C" void kernel_launch(void* const* d_in, const int* in_sizes, int n_in,
                              void* d_out, int out_size) {
    const float* lat = (const float*)d_in[0];
    const float* emb = (const float*)d_in[1];
    if (n_in >= 2 && in_sizes[0] == D_ * K_) {   // defensive size-based ident
        lat = (const float*)d_in[1];
        emb = (const float*)d_in[0];
    }
    float* out = (float*)d_out;

    embprep_kernel<<<K_ / 256, 256>>>(emb);
    latconv_kernel<<<dim3(HW / 32, D_ / 32, B_), dim3(32, 32)>>>(lat);
    embT_kernel<<<dim3(K_ / 32, D_ / 32), dim3(32, 32)>>>(emb);

    // vq_mma stays the 4th launch so ncu's skip window profiles it.
    cudaFuncSetAttribute(vq_mma_kernel,
                         cudaFuncAttributeMaxDynamicSharedMemorySize, SM_TOTAL);
    vq_mma_kernel<<<N_ / 128, 512, SM_TOTAL>>>();

    cudaFuncSetAttribute(rescore_gather_kernel,
                         cudaFuncAttributeMaxDynamicSharedMemorySize, SMF_TOTAL);
    rescore_gather_kernel<<<B_ * 32, 256, SMF_TOTAL>>>(lat, out, out + IDX_OFF);
    loss_kernel<<<1, 1024>>>(out + LOSS_OFF);
}

// round 17
// speedup vs baseline: 1.4653x; 1.2078x over previous
#include <cuda_runtime.h>
#include <cuda_bf16.h>
#include <cstdint>
#include <float.h>

// ---------------------------------------------------------------- problem dims
#define B_  32
#define D_  256
#define K_  8192
#define HW  1024
#define N_  32768
#define OUT_ELEMS 8388608
#define LOSS_OFF  OUT_ELEMS
#define IDX_OFF   (OUT_ELEMS + 1)

// ---------------------------------------------------------------- GEMM tiling (int8)
#define NCHUNK 64                    // 64 chunks of 128 codes (32 per warp pair)
#define AROW 272                     // bytes per A smem row (256 s8 + 16 pad)
#define SROW 272                     // bytes per B-slice row (256 s8 + 16 pad)
#define SLICE_BUF (32 * SROW)        // 8704: one 32-code x 256-d s8 slice
#define SM_A 0
#define SM_S (128 * AROW)            // 34816
#define SM_TOTAL (SM_S + 8 * SLICE_BUF)  // 104448

#define EBIAS 1024.0f                // fp32 enorm bias (argmin invariant)
#define QSCALE 25.4f                 // 127 / 5 sigma
#define BIAS_I (1 << 19)             // integer score bias (covers |zq|^2)
#define NCAND 16                     // rescored candidates per row

// ---------------------------------------------------------------- scratch
__device__ __align__(16) float g_enorm[K_];                       // ||e||^2 + EBIAS (fp32, rescore)
__device__ __align__(16) int   g_enormI[K_];                      // (sum eq^2 + BIAS_I) << 9
__device__ __align__(16) int   g_idx[N_];
__device__ __align__(16) float g_part[1024];
__device__ __align__(16) int   g_top16[N_ * NCAND];
__device__ __align__(16) signed char g_latQ8[(size_t)N_ * D_];    // [n][d] s8
__device__ __align__(16) signed char g_embQ8[(size_t)K_ * D_];    // [k][d] s8 (code-major)
__device__ __align__(16) float g_embT[(size_t)K_ * D_];           // [k][d] fp32

// ---------------------------------------------------------------- helpers
__device__ __forceinline__ uint32_t smem_u32(const void* p) {
    return (uint32_t)__cvta_generic_to_shared(p);
}
__device__ __forceinline__ void cp_async16(uint32_t dst, const void* src) {
    asm volatile("cp.async.cg.shared.global [%0], [%1], 16;" :: "r"(dst), "l"(src));
}
__device__ __forceinline__ void ldsm_x4(uint32_t* r, uint32_t addr) {
    asm volatile("ldmatrix.sync.aligned.m8n8.x4.shared.b16 {%0,%1,%2,%3}, [%4];"
                 : "=r"(r[0]), "=r"(r[1]), "=r"(r[2]), "=r"(r[3]) : "r"(addr));
}
// int8 MMA: D[16x8] += A[16x32] * B[32x8], s32 accum (fragment layout = 8-bit m16n8k32)
__device__ __forceinline__ void mma_s8(int* c, const uint32_t* a, uint32_t b0, uint32_t b1) {
    asm volatile(
        "mma.sync.aligned.m16n8k32.row.col.s32.s8.s8.s32 "
        "{%0,%1,%2,%3}, {%4,%5,%6,%7}, {%8,%9}, {%0,%1,%2,%3};"
        : "+r"(c[0]), "+r"(c[1]), "+r"(c[2]), "+r"(c[3])
        : "r"(a[0]), "r"(a[1]), "r"(a[2]), "r"(a[3]), "r"(b0), "r"(b1));
}
#define PAIR_BAR(wn) \
    asm volatile("bar.sync %0, 64;" :: "r"(1 + (wn)) : "memory")
__device__ __forceinline__ int quant8(float v) {
    int q = __float2int_rn(v * QSCALE);
    return q > 127 ? 127 : (q < -127 ? -127 : q);
}

// ---------------------------------------------------------------- kernel 1: enorm (fp32 biased) + integer enorm of quantized e
__global__ __launch_bounds__(256)
void enorm_kernel(const float* __restrict__ emb) {
    int k = blockIdx.x * 256 + threadIdx.x;
    float s = 0.f;
    int qs = 0;
#pragma unroll 8
    for (int d = 0; d < D_; ++d) {
        float v = emb[(size_t)d * K_ + k];
        s = fmaf(v, v, s);
        int q = quant8(v);
        qs += q * q;
    }
    g_enorm[k]  = s + EBIAS;
    g_enormI[k] = (qs + BIAS_I) << 9;
}

// ---------------------------------------------------------------- kernel 2: latents -> s8 [n][d]
__global__ void latconv_kernel(const float* __restrict__ lat) {
    __shared__ float t[32][33];
    int b = blockIdx.z, hw0 = blockIdx.x * 32, d0 = blockIdx.y * 32;
    t[threadIdx.y][threadIdx.x] =
        lat[((size_t)b * D_ + d0 + threadIdx.y) * HW + hw0 + threadIdx.x];
    __syncthreads();
    g_latQ8[((size_t)(b * HW + hw0 + threadIdx.y)) * D_ + d0 + threadIdx.x] =
        (signed char)quant8(t[threadIdx.x][threadIdx.y]);
}

// ---------------------------------------------------------------- kernel 3: embeddings -> fp32 + s8, both [k][d] code-major
__global__ void embT_kernel(const float* __restrict__ emb) {
    __shared__ float t[32][33];
    int kb = blockIdx.x * 32, db = blockIdx.y * 32;
    t[threadIdx.y][threadIdx.x] = emb[(size_t)(db + threadIdx.y) * K_ + kb + threadIdx.x];
    __syncthreads();
    float v = t[threadIdx.x][threadIdx.y];
    size_t o = (size_t)(kb + threadIdx.y) * D_ + db + threadIdx.x;
    g_embT[o]  = v;
    g_embQ8[o] = (signed char)quant8(v);
}

// ---------------------------------------------------------------- kernel 4 support
__device__ __forceinline__ void prefetch_slice(uint32_t bufaddr, int lane, int wm,
                                               int code_base) {
    const char* base = (const char*)g_embQ8 + (size_t)code_base * 256;
#pragma unroll
    for (int j = 0; j < 8; ++j) {
        int idx = j * 32 + lane;
        int r = (idx >> 4) + wm * 16, s = idx & 15;
        cp_async16(bufaddr + r * SROW + s * 16, base + (size_t)r * 256 + s * 16);
    }
    asm volatile("cp.async.commit_group;" ::: "memory");
}

// Packed top-3 (u32 min/max network). pv = exact integer score<<9 | local id.
#define TOP3P(rs, pv_)                                        \
    {                                                         \
        uint32_t t1_ = p0[rs] > (pv_) ? p0[rs] : (pv_);       \
        p0[rs] = p0[rs] < (pv_) ? p0[rs] : (pv_);             \
        uint32_t t2_ = p1[rs] > t1_ ? p1[rs] : t1_;           \
        p1[rs] = p1[rs] < t1_ ? p1[rs] : t1_;                 \
        p2[rs] = p2[rs] < t2_ ? p2[rs] : t2_;                 \
    }

// One chunk (8 k-steps of K=32) into A; optionally interleave prev chunk's
// integer epilogue (P): 2 groups per k-step -> all 16 (mf,nf) in HMMA shadow.
// pv = (enormI + BIAS)<<9 + c9 - (dot<<10): exact int, monotone in score,
// ties -> smaller local id = earlier column (first-occurrence).
template<bool EPI>
__device__ __forceinline__ void mma_chunk(
    int (&A)[4][4][4], int (&P)[4][4][4],
    uint32_t bbase, const uint32_t* a_addr,
    int cb0_prev, uint32_t u9_prev,
    uint32_t* p0, uint32_t* p1, uint32_t* p2)
{
#pragma unroll
    for (int mf = 0; mf < 4; ++mf)
#pragma unroll
        for (int nf = 0; nf < 4; ++nf)
#pragma unroll
            for (int q = 0; q < 4; ++q) A[mf][nf][q] = 0;

#pragma unroll
    for (int ks = 0; ks < 8; ++ks) {
        uint32_t ar[4][4];
#pragma unroll
        for (int mf = 0; mf < 4; ++mf) ldsm_x4(ar[mf], a_addr[mf] + ks * 32);
        uint32_t br[2][4];
#pragma unroll
        for (int p = 0; p < 2; ++p)
            ldsm_x4(br[p], bbase + p * (16 * SROW) + ks * 32);
#pragma unroll
        for (int mf = 0; mf < 4; ++mf)
#pragma unroll
            for (int nf = 0; nf < 4; ++nf)
                mma_s8(A[mf][nf], ar[mf],
                       br[nf >> 1][(nf & 1) * 2], br[nf >> 1][(nf & 1) * 2 + 1]);

        if (EPI) {
#pragma unroll
            for (int g = 0; g < 2; ++g) {
                const int gg = ks * 2 + g;
                const int mf = gg & 3, nf = gg >> 2;
                const int c0 = cb0_prev + nf * 8;
                const int c9 = (int)(u9_prev + nf * 2);
                int2 e = __ldg(reinterpret_cast<const int2*>(&g_enormI[c0]));
                const int ec0 = e.x + c9, ec1 = e.y + c9 + 1;
#pragma unroll
                for (int half = 0; half < 2; ++half) {
                    const int rs = mf * 2 + half;
                    uint32_t v0 = (uint32_t)(ec0 - (P[mf][nf][half * 2 + 0] << 10));
                    uint32_t v1 = (uint32_t)(ec1 - (P[mf][nf][half * 2 + 1] << 10));
                    TOP3P(rs, v0);
                    TOP3P(rs, v1);
                }
            }
        }
    }
}

__device__ __forceinline__ void epi_chunk(
    int (&P)[4][4][4], int cb0, uint32_t u9,
    uint32_t* p0, uint32_t* p1, uint32_t* p2)
{
#pragma unroll
    for (int nf = 0; nf < 4; ++nf) {
        const int c0 = cb0 + nf * 8;
        const int c9 = (int)(u9 + nf * 2);
        int2 e = __ldg(reinterpret_cast<const int2*>(&g_enormI[c0]));
        const int ec0 = e.x + c9, ec1 = e.y + c9 + 1;
#pragma unroll
        for (int mf = 0; mf < 4; ++mf)
#pragma unroll
            for (int half = 0; half < 2; ++half) {
                const int rs = mf * 2 + half;
                uint32_t v0 = (uint32_t)(ec0 - (P[mf][nf][half * 2 + 0] << 10));
                uint32_t v1 = (uint32_t)(ec1 - (P[mf][nf][half * 2 + 1] << 10));
                TOP3P(rs, v0);
                TOP3P(rs, v1);
            }
    }
}

// decode 9-bit local id (u<<3 | nf*2+q) back to a global column
__device__ __forceinline__ int dec9(uint32_t p, int wn, int l3) {
    int loc = p & 0x1FF;
    int u = loc >> 3, jj = loc & 7;
    return u * 128 + wn * 32 + l3 * 2 + (jj >> 1) * 8 + (jj & 1);
}

// ---------------------------------------------------------------- kernel 4: int8 mma.sync GEMM, pair-decoupled pipeline
__global__ __launch_bounds__(256, 1)
void vq_mma_kernel() {
    extern __shared__ char smem[];
    const uint32_t sb = smem_u32(smem);
    const int tid = threadIdx.x, lane = tid & 31, wid = tid >> 5;
    const int wm = wid & 1;        // 0-1: 64-row half (M)
    const int wn = wid >> 1;       // 0-3: 32-col quarter (N) = pair id

    const uint32_t pair_base = sb + SM_S + wn * (2 * SLICE_BUF);
    const uint32_t buf0 = pair_base, buf1 = pair_base + SLICE_BUF;
    const int colc = wn * 32;      // this pair's code offset within a chunk

    // ---- prologue: A tile (128x256 s8) + slice(chunk0); slice(chunk1)
    {
        const char* at = (const char*)g_latQ8 + (size_t)blockIdx.x * 128 * 256;
#pragma unroll
        for (int j = 0; j < 8; ++j) {
            int i = j * 256 + tid;
            int r = i >> 4, s = i & 15;
            cp_async16(sb + SM_A + r * AROW + s * 16, at + (size_t)r * 256 + s * 16);
        }
    }
    prefetch_slice(buf0, lane, wm, 0 * 128 + colc);
    prefetch_slice(buf1, lane, wm, 1 * 128 + colc);

    uint32_t a_addr[4];
#pragma unroll
    for (int mf = 0; mf < 4; ++mf)
        a_addr[mf] = sb + SM_A + (wm * 64 + mf * 16 + (lane & 15)) * AROW
                   + (lane >> 4) * 16;
    const uint32_t b_off = ((lane & 7) + (lane >> 4) * 8) * SROW
                         + ((lane >> 3) & 1) * 16;
    const int cb_lane = wn * 32 + (lane & 3) * 2;

    uint32_t p0[8], p1[8], p2[8];
#pragma unroll
    for (int r = 0; r < 8; ++r) {
        p0[r] = 0xFFFFFFFFu; p1[r] = 0xFFFFFFFFu; p2[r] = 0xFFFFFFFFu;
    }

    int accA[4][4][4], accB[4][4][4];

    asm volatile("cp.async.wait_group 1;" ::: "memory");   // A + slice0 landed (own)
    __syncthreads();                                       // everyone's visible

    mma_chunk<false>(accA, accA, buf0 + b_off, a_addr, 0, 0, p0, p1, p2);

    // ---- pair-local pipeline: no block-wide syncs in the mainloop
    for (int u = 0; u < 62; u += 2) {
        PAIR_BAR(wn);
        prefetch_slice(buf0, lane, wm, (u + 2) * 128 + colc);
        asm volatile("cp.async.wait_group 1;" ::: "memory");
        PAIR_BAR(wn);
        mma_chunk<true>(accB, accA, buf1 + b_off, a_addr,
                        (u << 7) + cb_lane, (uint32_t)(u << 3), p0, p1, p2);

        PAIR_BAR(wn);
        prefetch_slice(buf1, lane, wm, (u + 3) * 128 + colc);
        asm volatile("cp.async.wait_group 1;" ::: "memory");
        PAIR_BAR(wn);
        mma_chunk<true>(accA, accB, buf0 + b_off, a_addr,
                        ((u + 1) << 7) + cb_lane, (uint32_t)((u + 1) << 3), p0, p1, p2);
    }

    PAIR_BAR(wn);
    asm volatile("cp.async.wait_group 0;" ::: "memory");
    PAIR_BAR(wn);
    mma_chunk<true>(accB, accA, buf1 + b_off, a_addr,
                    (62 << 7) + cb_lane, (uint32_t)(62 << 3), p0, p1, p2);
    epi_chunk(accB, (63 << 7) + cb_lane, (uint32_t)(63 << 3), p0, p1, p2);

    // ---- merge: 16 subsets x top-3 = 48 per row -> keep 16 smallest.
    // Entries: truncated score bits | 13-bit global id (u32-monotone; ties ->
    // smaller index). Exact fp32 rescore of the 16 decides the final argmin.
    uint32_t* pr = reinterpret_cast<uint32_t*>(smem);   // [128][48] = 24KB (A done)
    const int l3 = lane & 3;
    __syncthreads();        // ALL pairs done with mainloop -> A region reusable
#pragma unroll
    for (int rs = 0; rs < 8; ++rs) {
        int r = wm * 64 + (rs >> 1) * 16 + (lane >> 2) + (rs & 1) * 8;
        int sub = wn * 4 + l3;
        pr[r * 48 + sub * 3 + 0] =
            (p0[rs] & 0xFFFFE000u) | (uint32_t)dec9(p0[rs], wn, l3);
        pr[r * 48 + sub * 3 + 1] =
            (p1[rs] & 0xFFFFE000u) | (uint32_t)dec9(p1[rs], wn, l3);
        pr[r * 48 + sub * 3 + 2] =
            (p2[rs] & 0xFFFFE000u) | (uint32_t)dec9(p2[rs], wn, l3);
    }
    __syncthreads();
    if (tid < 128) {
        uint32_t bv[NCAND];
#pragma unroll
        for (int s = 0; s < NCAND; ++s) bv[s] = 0xFFFFFFFFu;
        for (int j = 0; j < 48; ++j) {
            uint32_t v = pr[tid * 48 + j];
            if (v < bv[NCAND - 1]) {
                bv[NCAND - 1] = v;
#pragma unroll
                for (int s = NCAND - 1; s > 0; --s) {
                    uint32_t lo = bv[s - 1] < bv[s] ? bv[s - 1] : bv[s];
                    uint32_t hi = bv[s - 1] < bv[s] ? bv[s] : bv[s - 1];
                    bv[s - 1] = lo; bv[s] = hi;
                }
            }
        }
        int row = blockIdx.x * 128 + tid;
#pragma unroll
        for (int s = 0; s < NCAND; ++s)
            g_top16[row * NCAND + s] = (int)(bv[s] & 0x1FFFu);
    }
}

// ---------------------------------------------------------------- kernel 5: fused exact rescore(16) + gather + loss partials
#define SMF_Z 0
#define SMF_E (32 * 257)
#define SMF_TOTAL ((2 * 32 * 257 + 32 + 256) * 4)
__global__ __launch_bounds__(256)
void rescore_gather_kernel(const float* __restrict__ lat,
                           float* __restrict__ out, float* __restrict__ out_idx_f) {
    extern __shared__ float sm[];
    float* zt = sm + SMF_Z;            // [32 rows][257 d] fp32 latents
    float* et = sm + SMF_E;            // [32 rows][257 d] gathered embeddings
    int*   sidx = (int*)(sm + 2 * 32 * 257);
    float* red  = sm + 2 * 32 * 257 + 32;

    int bh = blockIdx.x;               // (b,h)
    int b = bh >> 5, h = bh & 31;
    int t = threadIdx.x;
    int w = t & 31, dq = t >> 5;

    size_t base = (size_t)b * (D_ * HW) + h * 32;
#pragma unroll 4
    for (int i = 0; i < 32; ++i) {
        int d = i * 8 + dq;
        zt[w * 257 + d] = lat[base + (size_t)d * HW + w];
    }
    __syncthreads();

    // phase 1: exact fp32 rescore of 16 candidates — 8 threads per row, each
    // owning a contiguous 32-dim block (float4 embT loads; z in registers).
    {
        int rl = t >> 3, l8 = t & 7;
        int row = bh * 32 + rl;
        int cand[NCAND];
#pragma unroll
        for (int c = 0; c < NCAND; ++c) cand[c] = g_top16[row * NCAND + c];

        float zr[32];
#pragma unroll
        for (int q = 0; q < 32; ++q) zr[q] = zt[rl * 257 + l8 * 32 + q];

        float dot[NCAND];
#pragma unroll
        for (int c = 0; c < NCAND; ++c) {
            const float4* ep = reinterpret_cast<const float4*>(
                &g_embT[(size_t)cand[c] * D_ + l8 * 32]);
            float s = 0.f;
#pragma unroll
            for (int q = 0; q < 8; ++q) {
                float4 e4 = __ldg(&ep[q]);
                s = fmaf(zr[q * 4 + 0], e4.x, s);
                s = fmaf(zr[q * 4 + 1], e4.y, s);
                s = fmaf(zr[q * 4 + 2], e4.z, s);
                s = fmaf(zr[q * 4 + 3], e4.w, s);
            }
            dot[c] = s;
        }
#pragma unroll
        for (int c = 0; c < NCAND; ++c) {
#pragma unroll
            for (int off = 4; off > 0; off >>= 1)
                dot[c] += __shfl_down_sync(0xffffffffu, dot[c], off, 8);
        }
        if (l8 == 0) {
            float bv = FLT_MAX; int bi = 0x7fffffff;
#pragma unroll
            for (int c = 0; c < NCAND; ++c) {
                float dist = fmaf(-2.f, dot[c], g_enorm[cand[c]]);  // bias invariant
                if (dist < bv || (dist == bv && cand[c] < bi)) { bv = dist; bi = cand[c]; }
            }
            g_idx[row] = bi;
            sidx[rl] = bi;
            out_idx_f[row] = (float)bi;
        }
    }
    __syncthreads();

#pragma unroll 4
    for (int i = 0; i < 32; ++i)
        et[i * 257 + t] = g_embT[(size_t)sidx[i] * D_ + t];
    __syncthreads();

    float lsum = 0.f;
#pragma unroll 4
    for (int i = 0; i < 32; ++i) {
        int d = i * 8 + dq;
        float v = et[w * 257 + d];
        float x = zt[w * 257 + d];
        out[base + (size_t)d * HW + w] = v;
        float df = v - x;
        lsum = fmaf(df, df, lsum);
    }
    red[t] = lsum;
    __syncthreads();
    for (int st = 128; st > 0; st >>= 1) {
        if (t < st) red[t] += red[t + st];
        __syncthreads();
    }
    if (t == 0) g_part[bh] = red[0];
}

// ---------------------------------------------------------------- kernel 6: final loss
__global__ void loss_kernel(float* __restrict__ out_loss) {
    __shared__ float red[1024];
    int t = threadIdx.x;
    red[t] = g_part[t];
    __syncthreads();
    for (int st = 512; st > 0; st >>= 1) {
        if (t < st) red[t] += red[t + st];
        __syncthreads();
    }
    if (t == 0) out_loss[0] = 1.25f * (red[0] / 8388608.0f);
}

// ----------------------------------------------------------------
extern "C" void kernel_launch(void* const* d_in, const int* in_sizes, int n_in,
                              void* d_out, int out_size) {
    const float* lat = (const float*)d_in[0];
    const float* emb = (const float*)d_in[1];
    if (n_in >= 2 && in_sizes[0] == D_ * K_) {   // defensive size-based ident
        lat = (const float*)d_in[1];
        emb = (const float*)d_in[0];
    }
    float* out = (float*)d_out;

    enorm_kernel<<<K_ / 256, 256>>>(emb);
    latconv_kernel<<<dim3(HW / 32, D_ / 32, B_), dim3(32, 32)>>>(lat);
    embT_kernel<<<dim3(K_ / 32, D_ / 32), dim3(32, 32)>>>(emb);

    // vq_mma stays the 4th launch so ncu's skip window profiles it.
    cudaFuncSetAttribute(vq_mma_kernel,
                         cudaFuncAttributeMaxDynamicSharedMemorySize, SM_TOTAL);
    vq_mma_kernel<<<N_ / 128, 256, SM_TOTAL>>>();

    cudaFuncSetAttribute(rescore_gather_kernel,
                         cudaFuncAttributeMaxDynamicSharedMemorySize, SMF_TOTAL);
    rescore_gather_kernel<<<B_ * 32, 256, SMF_TOTAL>>>(lat, out, out + IDX_OFF);
    loss_kernel<<<1, 1024>>>(out + LOSS_OFF);
}